// round 1
// baseline (speedup 1.0000x reference)
#include <cuda_runtime.h>
#include <cstdint>

// Problem constants (fixed shapes per reference)
#define BATCH    512
#define BITD     64
#define NCLS     100
#define NTRAIN   100000
#define MARGIN_F 128.0f

#define SCAN_BLOCKS 391          // ceil(100000/256)
#define UST_BLOCKS  160
#define MAIN_BLOCKS (SCAN_BLOCKS + UST_BLOCKS)

// -------- device accumulators / scratch (no allocations allowed) --------
__device__ double g_sum_usq;          // sum_b |u_b|^2
__device__ double g_s2;               // sum |1 - sign(u)|
__device__ double g_SUsq;             // sum_n |U'_n|^2  (after update)
__device__ double g_corr;             // hinge correction over mismatch pairs
__device__ double g_su[BITD];         // column sums of u
__device__ double g_SU[BITD];         // column sums of U' (after update)
__device__ float    g_usq[BATCH];     // per-row |u_b|^2
__device__ unsigned g_ypk[4 * BATCH]; // packed batch labels, word-major [w][b]
__device__ int      g_map[NTRAIN];    // n -> batch row that overwrote it (-1 none)

// ---------------------------------------------------------------- init
__global__ void k_init() {
    int n = blockIdx.x * blockDim.x + threadIdx.x;
    if (n < NTRAIN) g_map[n] = -1;
    if (n < BITD) { g_su[n] = 0.0; g_SU[n] = 0.0; }
    if (n == 0) { g_sum_usq = 0.0; g_s2 = 0.0; g_SUsq = 0.0; g_corr = 0.0; }
}

// ------------------------------------------------- batch stats + y pack
__global__ void k_batch(const float* __restrict__ u,
                        const float* __restrict__ y,
                        const int*   __restrict__ ind) {
    __shared__ float ssu[BITD];
    int i = threadIdx.x;                       // 512 threads, 1 block
    if (i < BITD) ssu[i] = 0.f;
    __syncthreads();

    atomicMax(&g_map[ind[i]], i);              // last-writer wins (max index)

    const float* ur = u + i * BITD;
    float usq = 0.f, s2 = 0.f;
#pragma unroll
    for (int k = 0; k < BITD; k++) {
        float v = ur[k];
        usq += v * v;
        s2  += (v > 0.f) ? 0.f : ((v < 0.f) ? 2.f : 1.f);
        atomicAdd(&ssu[k], v);
    }
    g_usq[i] = usq;
    atomicAdd(&g_sum_usq, (double)usq);
    atomicAdd(&g_s2, (double)s2);

    // pack this thread's y row into 4 words (bit c set iff y[c] != 0)
    const float* yr = y + (size_t)i * NCLS;
    unsigned w0 = 0, w1 = 0, w2 = 0, w3 = 0;
#pragma unroll
    for (int c = 0; c < 32; c++) {
        if (yr[c]        != 0.f) w0 |= 1u << c;
        if (yr[32 + c]   != 0.f) w1 |= 1u << c;
        if (yr[64 + c]   != 0.f) w2 |= 1u << c;
    }
#pragma unroll
    for (int c = 0; c < 4; c++)
        if (yr[96 + c] != 0.f) w3 |= 1u << c;
    g_ypk[i]              = w0;
    g_ypk[BATCH + i]      = w1;
    g_ypk[2 * BATCH + i]  = w2;
    g_ypk[3 * BATCH + i]  = w3;

    __syncthreads();
    if (i < BITD) atomicAdd(&g_su[i], (double)ssu[i]);
}

// --------------------------------------- rare path: exact pair correction
__device__ __noinline__ double mismatch_fix(int b, int n,
                                            const float* __restrict__ u,
                                            const float* __restrict__ U) {
    const float* ur = u + b * BITD;
    int m = g_map[n];
    const float* vr = (m >= 0) ? (u + m * BITD) : (U + (size_t)n * BITD);
    float dot = 0.f, vsq = 0.f;
#pragma unroll 16
    for (int k = 0; k < BITD; k++) {
        float a = ur[k], c = vr[k];
        dot = fmaf(a, c, dot);
        vsq = fmaf(c, c, vsq);
    }
    float d = g_usq[b] - 2.f * dot + vsq;
    d = fmaxf(d, 0.f);
    // pair's loss changes from 0.5*d (counted in closed form) to 0.5*max(m-d,0)
    return 0.5 * ((double)fmaxf(MARGIN_F - d, 0.f) - (double)d);
}

// ------------- fused kernel: [scan blocks] mismatch scan with inline Y pack
//               [ustats blocks] column sums + sum of squares of U
__global__ void __launch_bounds__(256)
k_main(const float* __restrict__ u, const float* __restrict__ y,
       const float* __restrict__ U, const float* __restrict__ Y) {
    __shared__ unsigned sh[4 * BATCH];         // 8KB; also reused as float staging

    if (blockIdx.x >= SCAN_BLOCKS) {
        // ---------------- U stats role ----------------
        int lane  = threadIdx.x & 31;
        int warp  = threadIdx.x >> 5;
        int lwarp = (blockIdx.x - SCAN_BLOCKS) * 8 + warp;
        const int totw = UST_BLOCKS * 8;
        float c0 = 0.f, c1 = 0.f, sq = 0.f;
        for (int n = lwarp; n < NTRAIN; n += totw) {
            float2 v = *(const float2*)(U + (size_t)n * BITD + lane * 2);
            c0 += v.x; c1 += v.y;
            sq += v.x * v.x + v.y * v.y;
        }
#pragma unroll
        for (int o = 16; o; o >>= 1) sq += __shfl_xor_sync(0xffffffffu, sq, o);

        float* sc  = (float*)sh;               // [64] column partials
        float* swq = ((float*)sh) + 64;        // [8] per-warp sq
        if (threadIdx.x < 72) sc[threadIdx.x] = 0.f;
        __syncthreads();
        atomicAdd(&sc[lane * 2],     c0);
        atomicAdd(&sc[lane * 2 + 1], c1);
        if (lane == 0) swq[warp] = sq;
        __syncthreads();
        if (threadIdx.x < BITD) atomicAdd(&g_SU[threadIdx.x], (double)sc[threadIdx.x]);
        if (threadIdx.x == 0) {
            float s = 0.f;
#pragma unroll
            for (int w = 0; w < 8; w++) s += swq[w];
            atomicAdd(&g_SUsq, (double)s);
        }
        return;
    }

    // ---------------- scan role ----------------
    int t = threadIdx.x;
    for (int i = t; i < BATCH; i += 256) {
        sh[i]             = g_ypk[i];
        sh[BATCH + i]     = g_ypk[BATCH + i];
        sh[2 * BATCH + i] = g_ypk[2 * BATCH + i];
        sh[3 * BATCH + i] = g_ypk[3 * BATCH + i];
    }

    int n     = blockIdx.x * 256 + t;
    int lane  = t & 31;
    int warp  = t >> 5;
    int nbase = blockIdx.x * 256 + warp * 32;

    int mymap = (n < NTRAIN) ? g_map[n] : -1;

    // per-warp cooperative pack of this warp's 32 training rows (ballot)
    unsigned w0 = 0, w1 = 0, w2 = 0, w3 = 0;
    for (int r = 0; r < 32; r++) {
        int nr = nbase + r;
        int mr = __shfl_sync(0xffffffffu, mymap, r);
        const float* src;
        if (nr >= NTRAIN)     src = Y;                      // dummy, discarded
        else if (mr >= 0)     src = y + (size_t)mr * NCLS;  // overwritten by batch
        else                  src = Y + (size_t)nr * NCLS;
        float v0 = src[lane];
        float v1 = src[32 + lane];
        float v2 = src[64 + lane];
        float v3 = (lane < 4) ? src[96 + lane] : 0.f;
        unsigned b0 = __ballot_sync(0xffffffffu, v0 != 0.f);
        unsigned b1 = __ballot_sync(0xffffffffu, v1 != 0.f);
        unsigned b2 = __ballot_sync(0xffffffffu, v2 != 0.f);
        unsigned b3 = __ballot_sync(0xffffffffu, v3 != 0.f);
        if (lane == r) { w0 = b0; w1 = b1; w2 = b2; w3 = b3; }
    }
    __syncthreads();

    if (n >= NTRAIN) return;

    double corr = 0.0;
    const float* uu = u;
#pragma unroll 4
    for (int b0i = 0; b0i < BATCH; b0i += 8) {
        // "any zero AND in group of 8" via two min chains (ILP)
        unsigned mna = sh[b0i]     & w0;
        unsigned mnb = sh[b0i + 4] & w0;
#pragma unroll
        for (int j = 1; j < 4; j++) {
            mna = min(mna, sh[b0i + j]     & w0);
            mnb = min(mnb, sh[b0i + 4 + j] & w0);
        }
        if (min(mna, mnb) == 0u) {
#pragma unroll 1
            for (int j = 0; j < 8; j++) {
                int b = b0i + j;
                unsigned r = (sh[b] & w0) | (sh[BATCH + b] & w1) |
                             (sh[2 * BATCH + b] & w2) | (sh[3 * BATCH + b] & w3);
                if (r == 0u) corr += mismatch_fix(b, n, uu, U);
            }
        }
    }
    if (corr != 0.0) atomicAdd(&g_corr, corr);
}

// ----------------------- fix U stats for rows overwritten by the batch
__global__ void k_upd(const float* __restrict__ u,
                      const int*   __restrict__ ind,
                      const float* __restrict__ U) {
    int i = threadIdx.x;                       // 512 threads, 1 block
    int n = ind[i];
    if (g_map[n] != i) return;                 // only the last writer applies
    const float* ur = u + i * BITD;
    const float* Ur = U + (size_t)n * BITD;
    float dsq = 0.f;
#pragma unroll
    for (int k = 0; k < BITD; k++) {
        float a = ur[k], b = Ur[k];
        dsq += a * a - b * b;
        atomicAdd(&g_SU[k], (double)(a - b));
    }
    atomicAdd(&g_SUsq, (double)dsq);
}

// ---------------------------------------------------------- finalize
__global__ void k_final(float* __restrict__ out) {
    double dotsum = 0.0;
#pragma unroll
    for (int k = 0; k < BITD; k++) dotsum += g_su[k] * g_SU[k];
    double sum_dist = (double)NTRAIN * g_sum_usq
                    + (double)BATCH  * g_SUsq
                    - 2.0 * dotsum;
    double loss1 = (0.5 * sum_dist + g_corr) / ((double)BATCH * (double)NTRAIN);
    double loss2 = 0.1 * g_s2 / ((double)BATCH * (double)BITD);
    out[0] = (float)(loss1 + loss2);
}

// ------------------------------------------------------------ launcher
extern "C" void kernel_launch(void* const* d_in, const int* in_sizes, int n_in,
                              void* d_out, int out_size) {
    const float* u   = (const float*)d_in[0];   // [512, 64]
    const float* y   = (const float*)d_in[1];   // [512, 100]
    const int*   ind = (const int*)  d_in[2];   // [512]
    const float* U   = (const float*)d_in[3];   // [100000, 64]
    const float* Y   = (const float*)d_in[4];   // [100000, 100]
    float* out = (float*)d_out;

    k_init<<<(NTRAIN + 255) / 256, 256>>>();
    k_batch<<<1, BATCH>>>(u, y, ind);
    k_main<<<MAIN_BLOCKS, 256>>>(u, y, U, Y);
    k_upd<<<1, BATCH>>>(u, ind, U);
    k_final<<<1, 1>>>(out);
}